// round 1
// baseline (speedup 1.0000x reference)
#include <cuda_runtime.h>

#define NQ 4
#define TT 64
#define FF 32
#define HH 8
#define BMAX 2048

// scratch: x-projection  (B, T, NQ)
__device__ float g_xproj[BMAX * TT * NQ];

// CNOT ring permutation over basis indices (bit w = qubit w):
// b1^=b0; b2^=b1; b3^=b2; b0^=b3  (sequential)
__host__ __device__ constexpr int cnotF(int k) {
    int b0 = k & 1, b1 = (k >> 1) & 1, b2 = (k >> 2) & 1, b3 = (k >> 3) & 1;
    b1 ^= b0; b2 ^= b1; b3 ^= b2; b0 ^= b3;
    return b0 | (b1 << 1) | (b2 << 2) | (b3 << 3);
}
__host__ __device__ constexpr int popc4(int k) {
    return (k & 1) + ((k >> 1) & 1) + ((k >> 2) & 1) + ((k >> 3) & 1);
}

// ---------------------------------------------------------------------------
// Kernel 1: xproj[b,t,g] = b_in[g] + sum_f x[b,t,f] * w_in[g, 8+f]
// ---------------------------------------------------------------------------
__global__ void xproj_kernel(const float* __restrict__ x,
                             const float* __restrict__ w_in,
                             const float* __restrict__ b_in,
                             int n /* = B*T */) {
    __shared__ float sw[NQ][FF];
    __shared__ float sb[NQ];
    if (threadIdx.x < NQ * FF) {
        int g = threadIdx.x / FF, f = threadIdx.x % FF;
        sw[g][f] = w_in[g * (FF + HH) + HH + f];
    }
    if (threadIdx.x < NQ) sb[threadIdx.x] = b_in[threadIdx.x];
    __syncthreads();

    int idx = blockIdx.x * blockDim.x + threadIdx.x;
    if (idx >= n) return;
    const float* xr = x + (size_t)idx * FF;
    float a0 = sb[0], a1 = sb[1], a2 = sb[2], a3 = sb[3];
#pragma unroll
    for (int f = 0; f < FF; ++f) {
        float xv = xr[f];
        a0 = fmaf(xv, sw[0][f], a0);
        a1 = fmaf(xv, sw[1][f], a1);
        a2 = fmaf(xv, sw[2][f], a2);
        a3 = fmaf(xv, sw[3][f], a3);
    }
    float4 o = make_float4(a0, a1, a2, a3);
    reinterpret_cast<float4*>(g_xproj)[idx] = o;
}

// ---------------------------------------------------------------------------
// Kernel 2: recurrent QLSTM. 4 threads per batch element (one per gate).
// Circuit per gate (after folding layer-0 RX into the data angles):
//   product-state build (slots pre-permuted by CNOT ring F)
//   -> one RX layer (fixed angles W[1])
//   -> expectations with signs permuted by second ring F.
// ---------------------------------------------------------------------------
__global__ void __launch_bounds__(32, 1)
qlstm_kernel(const float* __restrict__ w_in,
             const float* __restrict__ w_out,
             const float* __restrict__ b_out,
             const float* __restrict__ wq_f, const float* __restrict__ wq_i,
             const float* __restrict__ wq_u, const float* __restrict__ wq_o,
             const float* __restrict__ w_fc, const float* __restrict__ b_fc,
             float* __restrict__ out, int B) {
    int tid  = blockIdx.x * 32 + threadIdx.x;
    int e0   = tid >> 2;
    int g    = tid & 3;
    int lane = threadIdx.x & 31;
    int base = lane & ~3;
    int e    = (e0 < B) ? e0 : (B - 1);

    const float* wq = (g == 0) ? wq_f : (g == 1) ? wq_i : (g == 2) ? wq_u : wq_o;

    // per-gate circuit constants
    float hw0[NQ], C1[NQ], S1[NQ];
#pragma unroll
    for (int w = 0; w < NQ; ++w) {
        hw0[w] = 0.5f * __ldg(&wq[w]);          // layer-0 half-angle (folded into data angle)
        float a = 0.5f * __ldg(&wq[NQ + w]);    // layer-1 half-angle
        C1[w] = cosf(a);
        S1[w] = sinf(a);
    }
    // y-projection weights for the h part
    float Win[NQ][HH];
#pragma unroll
    for (int w = 0; w < NQ; ++w)
#pragma unroll
        for (int j = 0; j < HH; ++j) Win[w][j] = __ldg(&w_in[w * (FF + HH) + j]);
    // output projection
    float Wout[HH][NQ], bo[HH];
#pragma unroll
    for (int hh = 0; hh < HH; ++hh) {
        bo[hh] = __ldg(&b_out[hh]);
#pragma unroll
        for (int w = 0; w < NQ; ++w) Wout[hh][w] = __ldg(&w_out[hh * NQ + w]);
    }

    float h[HH], cc[HH];
#pragma unroll
    for (int j = 0; j < HH; ++j) { h[j] = 0.f; cc[j] = 0.f; }

    // unified activation: sigmoid for f,i,o (g!=2), tanh for u (g==2)
    const float sc  = (g == 2) ? -2.f : -1.f;
    const float isT = (g == 2) ? 1.f : 0.f;

    const float* xpe = g_xproj + (size_t)e * (TT * NQ);

#pragma unroll 1
    for (int t = 0; t < TT; ++t) {
        // ---- y = xproj + h @ Win^T ; angles = 0.5*y + 0.5*W0 ----
        float4 xv = *reinterpret_cast<const float4*>(xpe + t * NQ);
        float y[NQ] = {xv.x, xv.y, xv.z, xv.w};
#pragma unroll
        for (int w = 0; w < NQ; ++w)
#pragma unroll
            for (int j = 0; j < HH; ++j) y[w] = fmaf(h[j], Win[w][j], y[w]);

        float cw[NQ], sw[NQ];
#pragma unroll
        for (int w = 0; w < NQ; ++w) {
            float ang = fmaf(0.5f, y[w], hw0[w]);
            __sincosf(ang, &sw[w], &cw[w]);
        }

        // ---- product-state build into ring-permuted slots ----
        float p01[4];
        p01[0] = cw[0] * cw[1]; p01[1] = sw[0] * cw[1];
        p01[2] = cw[0] * sw[1]; p01[3] = sw[0] * sw[1];
        float p012[8];
#pragma unroll
        for (int k = 0; k < 8; ++k) p012[k] = p01[k & 3] * ((k & 4) ? sw[2] : cw[2]);

        float ar[16], ai[16];
#pragma unroll
        for (int k = 0; k < 16; ++k) {
            float pk = p012[k & 7] * ((k & 8) ? sw[3] : cw[3]);
            const int s  = cnotF(k);          // slot after first CNOT ring
            const int pc = popc4(k) & 3;      // phase (-i)^popcount
            ar[s] = (pc == 0) ? pk : ((pc == 2) ? -pk : 0.f);
            ai[s] = (pc == 1) ? -pk : ((pc == 3) ? pk : 0.f);
        }

        // ---- one fixed RX layer (full complex) ----
#pragma unroll
        for (int w = 0; w < NQ; ++w) {
            const float C = C1[w], S = S1[w];
#pragma unroll
            for (int k = 0; k < 16; ++k) {
                if (k & (1 << w)) continue;
                const int j1 = k | (1 << w);
                float a0r = ar[k],  a0i = ai[k];
                float a1r = ar[j1], a1i = ai[j1];
                ar[k]  = fmaf(C, a0r,  S * a1i);
                ai[k]  = fmaf(C, a0i, -S * a1r);
                ar[j1] = fmaf(C, a1r,  S * a0i);
                ai[j1] = fmaf(C, a1i, -S * a0r);
            }
        }

        // ---- probabilities + Z expectations (second ring folded into signs) ----
        float ex[NQ] = {0.f, 0.f, 0.f, 0.f};
#pragma unroll
        for (int j = 0; j < 16; ++j) {
            float q = fmaf(ar[j], ar[j], ai[j] * ai[j]);
            const int m = cnotF(j);
#pragma unroll
            for (int w = 0; w < NQ; ++w)
                ex[w] += ((m >> w) & 1) ? -q : q;
        }

        // ---- gate vector + activation (own gate) ----
        float act[HH];
#pragma unroll
        for (int hh = 0; hh < HH; ++hh) {
            float gv = bo[hh];
#pragma unroll
            for (int w = 0; w < NQ; ++w) gv = fmaf(ex[w], Wout[hh][w], gv);
            float tE = __expf(sc * gv);
            act[hh] = __fdividef(fmaf(-isT, tE, 1.f), 1.f + tE);
        }

        // ---- gather all four gates' activated vectors ----
        float fv[HH], iv[HH], uv[HH], ov[HH];
#pragma unroll
        for (int j = 0; j < HH; ++j) {
            fv[j] = __shfl_sync(0xffffffffu, act[j], base + 0);
            iv[j] = __shfl_sync(0xffffffffu, act[j], base + 1);
            uv[j] = __shfl_sync(0xffffffffu, act[j], base + 2);
            ov[j] = __shfl_sync(0xffffffffu, act[j], base + 3);
        }

        // ---- cell update (c replicated; tanh split 2 components per lane) ----
#pragma unroll
        for (int j = 0; j < HH; ++j) cc[j] = fmaf(fv[j], cc[j], iv[j] * uv[j]);

        float ca = (g == 0) ? cc[0] : (g == 1) ? cc[2] : (g == 2) ? cc[4] : cc[6];
        float cb = (g == 0) ? cc[1] : (g == 1) ? cc[3] : (g == 2) ? cc[5] : cc[7];
        float oa = (g == 0) ? ov[0] : (g == 1) ? ov[2] : (g == 2) ? ov[4] : ov[6];
        float ob = (g == 0) ? ov[1] : (g == 1) ? ov[3] : (g == 2) ? ov[5] : ov[7];
        ca = fminf(fmaxf(ca, -15.f), 15.f);
        cb = fminf(fmaxf(cb, -15.f), 15.f);
        float e2a = __expf(-2.f * ca);
        float e2b = __expf(-2.f * cb);
        float ha = oa * __fdividef(1.f - e2a, 1.f + e2a);
        float hb = ob * __fdividef(1.f - e2b, 1.f + e2b);

        // broadcast h back to the whole 4-lane group
#pragma unroll
        for (int q2 = 0; q2 < 4; ++q2) {
            h[2 * q2]     = __shfl_sync(0xffffffffu, ha, base + q2);
            h[2 * q2 + 1] = __shfl_sync(0xffffffffu, hb, base + q2);
        }
    }

    // ---- final projection ----
    if (g == 0 && e0 < B) {
        float o = __ldg(&b_fc[0]);
#pragma unroll
        for (int j = 0; j < HH; ++j) o = fmaf(h[j], __ldg(&w_fc[j]), o);
        out[e] = o;
    }
}

// ---------------------------------------------------------------------------
extern "C" void kernel_launch(void* const* d_in, const int* in_sizes, int n_in,
                              void* d_out, int out_size) {
    const float* x     = (const float*)d_in[0];
    const float* w_in  = (const float*)d_in[1];
    const float* b_in  = (const float*)d_in[2];
    const float* w_out = (const float*)d_in[3];
    const float* b_out = (const float*)d_in[4];
    const float* wq_f  = (const float*)d_in[5];
    const float* wq_i  = (const float*)d_in[6];
    const float* wq_u  = (const float*)d_in[7];
    const float* wq_o  = (const float*)d_in[8];
    const float* w_fc  = (const float*)d_in[9];
    const float* b_fc  = (const float*)d_in[10];
    float* out = (float*)d_out;

    int B = in_sizes[0] / (TT * FF);
    if (B > BMAX) B = BMAX;

    int n = B * TT;
    xproj_kernel<<<(n + 255) / 256, 256>>>(x, w_in, b_in, n);

    int threads = B * 4;
    qlstm_kernel<<<(threads + 31) / 32, 32>>>(w_in, w_out, b_out,
                                              wq_f, wq_i, wq_u, wq_o,
                                              w_fc, b_fc, out, B);
}

// round 2
// speedup vs baseline: 1.0043x; 1.0043x over previous
#include <cuda_runtime.h>

#define NQ 4
#define TT 64
#define FF 32
#define HH 8
#define BMAX 2048

// scratch: x-projection  (B, T, NQ)
__device__ float g_xproj[BMAX * TT * NQ];

// CNOT ring permutation over basis indices (bit w = qubit w):
// b1^=b0; b2^=b1; b3^=b2; b0^=b3  (sequential)
__host__ __device__ constexpr int cnotF(int k) {
    int b0 = k & 1, b1 = (k >> 1) & 1, b2 = (k >> 2) & 1, b3 = (k >> 3) & 1;
    b1 ^= b0; b2 ^= b1; b3 ^= b2; b0 ^= b3;
    return b0 | (b1 << 1) | (b2 << 2) | (b3 << 3);
}
__host__ __device__ constexpr int popc4(int k) {
    return (k & 1) + ((k >> 1) & 1) + ((k >> 2) & 1) + ((k >> 3) & 1);
}

// ---------------------------------------------------------------------------
// Kernel 1: xproj[b,t,g] = b_in[g] + sum_f x[b,t,f] * w_in[g, 8+f]
// ---------------------------------------------------------------------------
__global__ void xproj_kernel(const float* __restrict__ x,
                             const float* __restrict__ w_in,
                             const float* __restrict__ b_in,
                             int n /* = B*T */) {
    __shared__ float sw[NQ][FF];
    __shared__ float sb[NQ];
    if (threadIdx.x < NQ * FF) {
        int g = threadIdx.x / FF, f = threadIdx.x % FF;
        sw[g][f] = w_in[g * (FF + HH) + HH + f];
    }
    if (threadIdx.x < NQ) sb[threadIdx.x] = b_in[threadIdx.x];
    __syncthreads();

    int idx = blockIdx.x * blockDim.x + threadIdx.x;
    if (idx >= n) return;
    const float* xr = x + (size_t)idx * FF;
    float a0 = sb[0], a1 = sb[1], a2 = sb[2], a3 = sb[3];
#pragma unroll
    for (int f = 0; f < FF; ++f) {
        float xv = xr[f];
        a0 = fmaf(xv, sw[0][f], a0);
        a1 = fmaf(xv, sw[1][f], a1);
        a2 = fmaf(xv, sw[2][f], a2);
        a3 = fmaf(xv, sw[3][f], a3);
    }
    float4 o = make_float4(a0, a1, a2, a3);
    reinterpret_cast<float4*>(g_xproj)[idx] = o;
}

// ---------------------------------------------------------------------------
// Kernel 2: recurrent QLSTM. 4 threads per batch element (one per gate).
// Circuit per gate (after folding layer-0 RX into the data angles):
//   product-state build (slots pre-permuted by CNOT ring F)
//   -> one RX layer (fixed angles W[1])
//   -> expectations with signs permuted by second ring F.
// ---------------------------------------------------------------------------
__global__ void __launch_bounds__(32, 1)
qlstm_kernel(const float* __restrict__ w_in,
             const float* __restrict__ w_out,
             const float* __restrict__ b_out,
             const float* __restrict__ wq_f, const float* __restrict__ wq_i,
             const float* __restrict__ wq_u, const float* __restrict__ wq_o,
             const float* __restrict__ w_fc, const float* __restrict__ b_fc,
             float* __restrict__ out, int B) {
    int tid  = blockIdx.x * 32 + threadIdx.x;
    int e0   = tid >> 2;
    int g    = tid & 3;
    int lane = threadIdx.x & 31;
    int base = lane & ~3;
    int e    = (e0 < B) ? e0 : (B - 1);

    const float* wq = (g == 0) ? wq_f : (g == 1) ? wq_i : (g == 2) ? wq_u : wq_o;

    // per-gate circuit constants
    float hw0[NQ], C1[NQ], S1[NQ];
#pragma unroll
    for (int w = 0; w < NQ; ++w) {
        hw0[w] = 0.5f * __ldg(&wq[w]);          // layer-0 half-angle (folded into data angle)
        float a = 0.5f * __ldg(&wq[NQ + w]);    // layer-1 half-angle
        C1[w] = cosf(a);
        S1[w] = sinf(a);
    }
    // y-projection weights for the h part
    float Win[NQ][HH];
#pragma unroll
    for (int w = 0; w < NQ; ++w)
#pragma unroll
        for (int j = 0; j < HH; ++j) Win[w][j] = __ldg(&w_in[w * (FF + HH) + j]);
    // output projection
    float Wout[HH][NQ], bo[HH];
#pragma unroll
    for (int hh = 0; hh < HH; ++hh) {
        bo[hh] = __ldg(&b_out[hh]);
#pragma unroll
        for (int w = 0; w < NQ; ++w) Wout[hh][w] = __ldg(&w_out[hh * NQ + w]);
    }

    float h[HH], cc[HH];
#pragma unroll
    for (int j = 0; j < HH; ++j) { h[j] = 0.f; cc[j] = 0.f; }

    // unified activation: sigmoid for f,i,o (g!=2), tanh for u (g==2)
    const float sc  = (g == 2) ? -2.f : -1.f;
    const float isT = (g == 2) ? 1.f : 0.f;

    const float* xpe = g_xproj + (size_t)e * (TT * NQ);

#pragma unroll 1
    for (int t = 0; t < TT; ++t) {
        // ---- y = xproj + h @ Win^T ; angles = 0.5*y + 0.5*W0 ----
        float4 xv = *reinterpret_cast<const float4*>(xpe + t * NQ);
        float y[NQ] = {xv.x, xv.y, xv.z, xv.w};
#pragma unroll
        for (int w = 0; w < NQ; ++w)
#pragma unroll
            for (int j = 0; j < HH; ++j) y[w] = fmaf(h[j], Win[w][j], y[w]);

        float cw[NQ], sw[NQ];
#pragma unroll
        for (int w = 0; w < NQ; ++w) {
            float ang = fmaf(0.5f, y[w], hw0[w]);
            __sincosf(ang, &sw[w], &cw[w]);
        }

        // ---- product-state build into ring-permuted slots ----
        float p01[4];
        p01[0] = cw[0] * cw[1]; p01[1] = sw[0] * cw[1];
        p01[2] = cw[0] * sw[1]; p01[3] = sw[0] * sw[1];
        float p012[8];
#pragma unroll
        for (int k = 0; k < 8; ++k) p012[k] = p01[k & 3] * ((k & 4) ? sw[2] : cw[2]);

        float ar[16], ai[16];
#pragma unroll
        for (int k = 0; k < 16; ++k) {
            float pk = p012[k & 7] * ((k & 8) ? sw[3] : cw[3]);
            const int s  = cnotF(k);          // slot after first CNOT ring
            const int pc = popc4(k) & 3;      // phase (-i)^popcount
            ar[s] = (pc == 0) ? pk : ((pc == 2) ? -pk : 0.f);
            ai[s] = (pc == 1) ? -pk : ((pc == 3) ? pk : 0.f);
        }

        // ---- one fixed RX layer (full complex) ----
#pragma unroll
        for (int w = 0; w < NQ; ++w) {
            const float C = C1[w], S = S1[w];
#pragma unroll
            for (int k = 0; k < 16; ++k) {
                if (k & (1 << w)) continue;
                const int j1 = k | (1 << w);
                float a0r = ar[k],  a0i = ai[k];
                float a1r = ar[j1], a1i = ai[j1];
                ar[k]  = fmaf(C, a0r,  S * a1i);
                ai[k]  = fmaf(C, a0i, -S * a1r);
                ar[j1] = fmaf(C, a1r,  S * a0i);
                ai[j1] = fmaf(C, a1i, -S * a0r);
            }
        }

        // ---- probabilities + Z expectations (second ring folded into signs) ----
        float ex[NQ] = {0.f, 0.f, 0.f, 0.f};
#pragma unroll
        for (int j = 0; j < 16; ++j) {
            float q = fmaf(ar[j], ar[j], ai[j] * ai[j]);
            const int m = cnotF(j);
#pragma unroll
            for (int w = 0; w < NQ; ++w)
                ex[w] += ((m >> w) & 1) ? -q : q;
        }

        // ---- gate vector + activation (own gate) ----
        float act[HH];
#pragma unroll
        for (int hh = 0; hh < HH; ++hh) {
            float gv = bo[hh];
#pragma unroll
            for (int w = 0; w < NQ; ++w) gv = fmaf(ex[w], Wout[hh][w], gv);
            float tE = __expf(sc * gv);
            act[hh] = __fdividef(fmaf(-isT, tE, 1.f), 1.f + tE);
        }

        // ---- gather all four gates' activated vectors ----
        float fv[HH], iv[HH], uv[HH], ov[HH];
#pragma unroll
        for (int j = 0; j < HH; ++j) {
            fv[j] = __shfl_sync(0xffffffffu, act[j], base + 0);
            iv[j] = __shfl_sync(0xffffffffu, act[j], base + 1);
            uv[j] = __shfl_sync(0xffffffffu, act[j], base + 2);
            ov[j] = __shfl_sync(0xffffffffu, act[j], base + 3);
        }

        // ---- cell update (c replicated; tanh split 2 components per lane) ----
#pragma unroll
        for (int j = 0; j < HH; ++j) cc[j] = fmaf(fv[j], cc[j], iv[j] * uv[j]);

        float ca = (g == 0) ? cc[0] : (g == 1) ? cc[2] : (g == 2) ? cc[4] : cc[6];
        float cb = (g == 0) ? cc[1] : (g == 1) ? cc[3] : (g == 2) ? cc[5] : cc[7];
        float oa = (g == 0) ? ov[0] : (g == 1) ? ov[2] : (g == 2) ? ov[4] : ov[6];
        float ob = (g == 0) ? ov[1] : (g == 1) ? ov[3] : (g == 2) ? ov[5] : ov[7];
        ca = fminf(fmaxf(ca, -15.f), 15.f);
        cb = fminf(fmaxf(cb, -15.f), 15.f);
        float e2a = __expf(-2.f * ca);
        float e2b = __expf(-2.f * cb);
        float ha = oa * __fdividef(1.f - e2a, 1.f + e2a);
        float hb = ob * __fdividef(1.f - e2b, 1.f + e2b);

        // broadcast h back to the whole 4-lane group
#pragma unroll
        for (int q2 = 0; q2 < 4; ++q2) {
            h[2 * q2]     = __shfl_sync(0xffffffffu, ha, base + q2);
            h[2 * q2 + 1] = __shfl_sync(0xffffffffu, hb, base + q2);
        }
    }

    // ---- final projection ----
    if (g == 0 && e0 < B) {
        float o = __ldg(&b_fc[0]);
#pragma unroll
        for (int j = 0; j < HH; ++j) o = fmaf(h[j], __ldg(&w_fc[j]), o);
        out[e] = o;
    }
}

// ---------------------------------------------------------------------------
extern "C" void kernel_launch(void* const* d_in, const int* in_sizes, int n_in,
                              void* d_out, int out_size) {
    const float* x     = (const float*)d_in[0];
    const float* w_in  = (const float*)d_in[1];
    const float* b_in  = (const float*)d_in[2];
    const float* w_out = (const float*)d_in[3];
    const float* b_out = (const float*)d_in[4];
    const float* wq_f  = (const float*)d_in[5];
    const float* wq_i  = (const float*)d_in[6];
    const float* wq_u  = (const float*)d_in[7];
    const float* wq_o  = (const float*)d_in[8];
    const float* w_fc  = (const float*)d_in[9];
    const float* b_fc  = (const float*)d_in[10];
    float* out = (float*)d_out;

    int B = in_sizes[0] / (TT * FF);
    if (B > BMAX) B = BMAX;

    int n = B * TT;
    xproj_kernel<<<(n + 255) / 256, 256>>>(x, w_in, b_in, n);

    int threads = B * 4;
    qlstm_kernel<<<(threads + 31) / 32, 32>>>(w_in, w_out, b_out,
                                              wq_f, wq_i, wq_u, wq_o,
                                              w_fc, b_fc, out, B);
}

// round 3
// speedup vs baseline: 1.9037x; 1.8956x over previous
#include <cuda_runtime.h>

#define TT 64
#define FULL 0xffffffffu

__host__ __device__ constexpr int cnotF(int k) {
    int b0 = k & 1, b1 = (k >> 1) & 1, b2 = (k >> 2) & 1, b3 = (k >> 3) & 1;
    b1 ^= b0; b2 ^= b1; b3 ^= b2; b0 ^= b3;
    return b0 | (b1 << 1) | (b2 << 2) | (b3 << 3);
}
__host__ __device__ constexpr int cnotFinv(int s) {
    int r = 0;
    for (int k = 0; k < 16; ++k) if (cnotF(k) == s) r = k;
    return r;
}
__host__ __device__ constexpr int popc4(int k) {
    return (k & 1) + ((k >> 1) & 1) + ((k >> 2) & 1) + ((k >> 3) & 1);
}

__device__ __forceinline__ float sx(float v, int m) { return __shfl_xor_sync(FULL, v, m); }

__global__ void __launch_bounds__(64, 1)
qlstm8(const float* __restrict__ x,
       const float* __restrict__ w_in,  const float* __restrict__ b_in,
       const float* __restrict__ w_out, const float* __restrict__ b_out,
       const float* __restrict__ wq_f,  const float* __restrict__ wq_i,
       const float* __restrict__ wq_u,  const float* __restrict__ wq_o,
       const float* __restrict__ w_fc,  const float* __restrict__ b_fc,
       float* __restrict__ out, int B)
{
    const int tid = blockIdx.x * 64 + threadIdx.x;
    const int e0  = tid >> 3;
    const int gl  = tid & 7;          // lane in 8-group
    const int g   = gl >> 1;          // gate
    const int hb  = gl & 1;           // amplitude half (slot bit3)
    const int b8  = (threadIdx.x & 31) & ~7;
    const int e   = (e0 < B) ? e0 : B - 1;

    const float* wq = (g == 0) ? wq_f : (g == 1) ? wq_i : (g == 2) ? wq_u : wq_o;

    // ---- constants ----
    float hw0[4], C[4], Sv[4];
#pragma unroll
    for (int w = 0; w < 4; ++w) {
        hw0[w] = 0.5f * (__ldg(&wq[w]) + __ldg(&b_in[w]));
        float a = 0.5f * __ldg(&wq[4 + w]);
        C[w] = cosf(a); Sv[w] = sinf(a);
    }
    float Wh[4][4], Wx[4][4];            // pre-scaled by 0.5
#pragma unroll
    for (int w = 0; w < 4; ++w)
#pragma unroll
        for (int j = 0; j < 4; ++j) {
            Wh[w][j] = 0.5f * __ldg(&w_in[w * 40 + 4 * hb + j]);
            Wx[w][j] = 0.5f * __ldg(&w_in[w * 40 + 8 + 4 * gl + j]);
        }
    float Wo[4][4], bo[4];
#pragma unroll
    for (int r = 0; r < 4; ++r) {
        bo[r] = __ldg(&b_out[4 * hb + r]);
#pragma unroll
        for (int w = 0; w < 4; ++w) Wo[r][w] = __ldg(&w_out[(4 * hb + r) * 4 + w]);
    }

    // ---- per-lane sign registers from phase-class tables ----
    const int flip = hb ? 11 : 0;        // Finv(8) = 11
    float sg3[8], t0[8], b1s[8], b2s[8];
#pragma unroll
    for (int u = 0; u < 8; ++u) {
        const int ku   = cnotFinv(u);
        const int cls  = popc4(ku ^ flip) & 3;
        const int clsp = popc4(ku ^ 11 ^ flip) & 3;
        const int c0   = popc4(cnotFinv(u ^ 1) ^ flip) & 3;
        const int c1   = popc4(cnotFinv(u ^ 2) ^ flip) & 3;
        const int c2   = popc4(cnotFinv(u ^ 4) ^ flip) & 3;
        sg3[u] = (((clsp + 1 - cls) & 3) == 0) ?  Sv[3] : -Sv[3];
        t0 [u] = (((c0 - cls) & 3) == 0)       ? -Sv[0] :  Sv[0];
        b1s[u] = (((c1 - cls) & 3) == 0)       ?  Sv[1] : -Sv[1];
        b2s[u] = (((c2 - cls) & 3) == 0)       ?  Sv[2] : -Sv[2];
    }
    const float fl03 = hb ? -1.f : 1.f;          // F(8)=9 flips exp signs on wires 0,3
    const float hm   = (g == 0) ? 1.f : 0.f;     // h-partial mask (count once)
    const float sc   = (g == 2) ? -2.f : -1.f;   // tanh for u-gate, sigmoid else
    const float isT  = (g == 2) ?  1.f :  0.f;

    float cc[4] = {0.f, 0.f, 0.f, 0.f};          // c comps [4hb..4hb+3]
    float hv[4] = {0.f, 0.f, 0.f, 0.f};          // h comps [4hb..4hb+3]

    const float4* xp = reinterpret_cast<const float4*>(x);
    const long xb = (long)e * TT * 8 + gl;
    float4 xc = __ldg(&xp[xb]);

#pragma unroll 1
    for (int t = 0; t < TT; ++t) {
        const int tn = (t + 1 < TT) ? t + 1 : t;
        float4 xn = __ldg(&xp[xb + (long)tn * 8]);

        // ---- angles: butterfly-reduced projection ----
        float pw[4];
#pragma unroll
        for (int w = 0; w < 4; ++w) {
            float hp = hv[0] * Wh[w][0];
            hp = fmaf(hv[1], Wh[w][1], hp);
            hp = fmaf(hv[2], Wh[w][2], hp);
            hp = fmaf(hv[3], Wh[w][3], hp);
            float a = hm * hp;
            a = fmaf(xc.x, Wx[w][0], a);
            a = fmaf(xc.y, Wx[w][1], a);
            a = fmaf(xc.z, Wx[w][2], a);
            a = fmaf(xc.w, Wx[w][3], a);
            pw[w] = a;
        }
#pragma unroll
        for (int st = 1; st <= 4; st <<= 1)
#pragma unroll
            for (int w = 0; w < 4; ++w) pw[w] += sx(pw[w], st);

        float cw[4], sw[4];
#pragma unroll
        for (int w = 0; w < 4; ++w) __sincosf(pw[w] + hw0[w], &sw[w], &cw[w]);

        // effective factors (hb swaps wires 0,1,3 via k ^= 11)
        float ec0 = hb ? sw[0] : cw[0], es0 = hb ? cw[0] : sw[0];
        float ec1 = hb ? sw[1] : cw[1], es1 = hb ? cw[1] : sw[1];
        float ec3 = hb ? sw[3] : cw[3], es3 = hb ? cw[3] : sw[3];

        // ---- product build (ring-permuted slots, pure residues) ----
        float r[8];
#pragma unroll
        for (int u = 0; u < 8; ++u) {
            const int k = cnotFinv(u);
            float f = ((k & 1) ? es0 : ec0) * ((k & 2) ? es1 : ec1);
            f *= (k & 4) ? sw[2] : cw[2];
            r[u] = f * ((k & 8) ? es3 : ec3);
        }

        // ---- RX wire 3: cross-lane real Givens ----
        float rp[8];
#pragma unroll
        for (int u = 0; u < 8; ++u) rp[u] = sx(r[u], 1);
#pragma unroll
        for (int u = 0; u < 8; ++u) r[u] = fmaf(C[3], r[u], sg3[u] * rp[u]);

        // ---- RX wire 0: pure -> complex ----
        float Re[8], Im[8];
#pragma unroll
        for (int u = 0; u < 8; ++u) { Re[u] = C[0] * r[u]; Im[u] = t0[u] * r[u ^ 1]; }

        // ---- RX wire 1 (pairs u, u^2) ----
#pragma unroll
        for (int u = 0; u < 8; ++u) {
            if (u & 2) continue;
            const int v = u | 2;
            float ar = Re[u], ai = Im[u], br = Re[v], bi = Im[v];
            Re[u] = fmaf(b1s[u], bi, C[1] * ar); Im[u] = fmaf(-b1s[u], br, C[1] * ai);
            Re[v] = fmaf(b1s[v], ai, C[1] * br); Im[v] = fmaf(-b1s[v], ar, C[1] * bi);
        }
        // ---- RX wire 2 (pairs u, u^4) ----
#pragma unroll
        for (int u = 0; u < 4; ++u) {
            const int v = u | 4;
            float ar = Re[u], ai = Im[u], br = Re[v], bi = Im[v];
            Re[u] = fmaf(b2s[u], bi, C[2] * ar); Im[u] = fmaf(-b2s[u], br, C[2] * ai);
            Re[v] = fmaf(b2s[v], ai, C[2] * br); Im[v] = fmaf(-b2s[v], ar, C[2] * bi);
        }

        // ---- probabilities + Walsh expectation partials ----
        float q[8];
#pragma unroll
        for (int u = 0; u < 8; ++u) q[u] = fmaf(Re[u], Re[u], Im[u] * Im[u]);
        float A = q[2] + q[3], Bp = q[4] + q[5], Cp = q[1] + q[2];
        float Dp = q[5] + q[6], Ep = q[4] + q[7];
        float S8 = ((q[0] + q[1]) + A) + (Bp + (q[6] + q[7]));
        float D0 = fmaf(-2.f, A + Bp, S8);
        float D1 = fmaf(-2.f, Cp + Dp, S8);
        float D2 = fmaf(-2.f, Cp + Ep, S8);
        float ex[4] = {fl03 * D0, D1, D2, fl03 * D2};
#pragma unroll
        for (int w = 0; w < 4; ++w) ex[w] += sx(ex[w], 1);

        // ---- own-gate activations for comps [4hb..4hb+3] ----
        float act[4];
#pragma unroll
        for (int rr = 0; rr < 4; ++rr) {
            float gv = bo[rr];
#pragma unroll
            for (int w = 0; w < 4; ++w) gv = fmaf(ex[w], Wo[rr][w], gv);
            float tE = __expf(sc * gv);
            act[rr] = __fdividef(fmaf(-isT, tE, 1.f), 1.f + tE);
        }

        // ---- gather f,i,u,o and update cell ----
#pragma unroll
        for (int rr = 0; rr < 4; ++rr) {
            float fv = __shfl_sync(FULL, act[rr], b8 + 0 + hb);
            float iv = __shfl_sync(FULL, act[rr], b8 + 2 + hb);
            float uv = __shfl_sync(FULL, act[rr], b8 + 4 + hb);
            float ov = __shfl_sync(FULL, act[rr], b8 + 6 + hb);
            float c2 = fmaf(fv, cc[rr], iv * uv);
            cc[rr] = c2;
            c2 = fminf(fmaxf(c2, -15.f), 15.f);
            float e2 = __expf(-2.f * c2);
            hv[rr] = ov * __fdividef(1.f - e2, 1.f + e2);
        }
        xc = xn;
    }

    // ---- final projection ----
    float p = hv[0] * __ldg(&w_fc[4 * hb]);
#pragma unroll
    for (int j = 1; j < 4; ++j) p = fmaf(hv[j], __ldg(&w_fc[4 * hb + j]), p);
    p += sx(p, 1);
    if (gl == 0 && e0 < B) out[e0] = p + __ldg(&b_fc[0]);
}

extern "C" void kernel_launch(void* const* d_in, const int* in_sizes, int n_in,
                              void* d_out, int out_size) {
    const float* x     = (const float*)d_in[0];
    const float* w_in  = (const float*)d_in[1];
    const float* b_in  = (const float*)d_in[2];
    const float* w_out = (const float*)d_in[3];
    const float* b_out = (const float*)d_in[4];
    const float* wq_f  = (const float*)d_in[5];
    const float* wq_i  = (const float*)d_in[6];
    const float* wq_u  = (const float*)d_in[7];
    const float* wq_o  = (const float*)d_in[8];
    const float* w_fc  = (const float*)d_in[9];
    const float* b_fc  = (const float*)d_in[10];

    int B = in_sizes[0] / (TT * 32);
    int threads = B * 8;
    int blocks = (threads + 63) / 64;
    qlstm8<<<blocks, 64>>>(x, w_in, b_in, w_out, b_out,
                           wq_f, wq_i, wq_u, wq_o, w_fc, b_fc,
                           (float*)d_out, B);
}

// round 4
// speedup vs baseline: 2.0468x; 1.0752x over previous
#include <cuda_runtime.h>

#define TT 64
#define FULL 0xffffffffu

__host__ __device__ constexpr int cnotF(int k) {
    int b0 = k & 1, b1 = (k >> 1) & 1, b2 = (k >> 2) & 1, b3 = (k >> 3) & 1;
    b1 ^= b0; b2 ^= b1; b3 ^= b2; b0 ^= b3;
    return b0 | (b1 << 1) | (b2 << 2) | (b3 << 3);
}
__host__ __device__ constexpr int cnotFinv(int s) {
    int r = 0;
    for (int k = 0; k < 16; ++k) if (cnotF(k) == s) r = k;
    return r;
}
__host__ __device__ constexpr int popc4(int k) {
    return (k & 1) + ((k >> 1) & 1) + ((k >> 2) & 1) + ((k >> 3) & 1);
}

__device__ __forceinline__ float sx(float v, int m) { return __shfl_xor_sync(FULL, v, m); }

__global__ void __launch_bounds__(128, 1)
qlstm16(const float* __restrict__ x,
        const float* __restrict__ w_in,  const float* __restrict__ b_in,
        const float* __restrict__ w_out, const float* __restrict__ b_out,
        const float* __restrict__ wq_f,  const float* __restrict__ wq_i,
        const float* __restrict__ wq_u,  const float* __restrict__ wq_o,
        const float* __restrict__ w_fc,  const float* __restrict__ b_fc,
        float* __restrict__ out, int B)
{
    const int tid = blockIdx.x * 128 + threadIdx.x;
    const int e0  = tid >> 4;
    const int gl  = tid & 15;         // lane in 16-group
    const int g   = gl >> 2;          // gate (f,i,u,o)
    const int sub = gl & 3;           // slot bits (3,2)
    const int b16 = (threadIdx.x & 31) & ~15;
    const int e   = (e0 < B) ? e0 : B - 1;

    const float* wq = (g == 0) ? wq_f : (g == 1) ? wq_i : (g == 2) ? wq_u : wq_o;

    // ---- circuit constants ----
    float hw0[4], C[4], Sv[4];
#pragma unroll
    for (int w = 0; w < 4; ++w) {
        hw0[w] = 0.5f * (__ldg(&wq[w]) + __ldg(&b_in[w]));
        float a = 0.5f * __ldg(&wq[4 + w]);
        C[w] = cosf(a); Sv[w] = sinf(a);
    }
    // projection weights (pre-scaled 0.5; h-part zeroed for gates != 0)
    float Wh[4][2], Wx[4][2];
    const float gmask = (g == 0) ? 0.5f : 0.f;
#pragma unroll
    for (int w = 0; w < 4; ++w)
#pragma unroll
        for (int j = 0; j < 2; ++j) {
            Wh[w][j] = gmask * __ldg(&w_in[w * 40 + 2 * sub + j]);
            Wx[w][j] = 0.5f  * __ldg(&w_in[w * 40 + 8 + 2 * gl + j]);
        }
    // output proj rows for comps {2*sub, 2*sub+1}, Hadamard characters folded in
    const float chiP = (popc4(sub) & 1) ? -1.f : 1.f;   // parity character
    const float chiB = (sub & 1) ? -1.f : 1.f;          // bit0 character
    const float chi[4] = {chiP, 1.f, chiB, chiP};       // wires 0..3
    float Wo[2][4], bo[2];
#pragma unroll
    for (int i = 0; i < 2; ++i) {
        bo[i] = __ldg(&b_out[2 * sub + i]);
#pragma unroll
        for (int w = 0; w < 4; ++w) Wo[i][w] = __ldg(&w_out[(2 * sub + i) * 4 + w]) * chi[w];
    }

    // ---- per-lane sign tables (slots s = 4*sub + u) ----
    const int FLIPT[4] = {0, 12, 11, 7};   // Finv(4*sub)
    const int flip = FLIPT[sub];
    float sg3[4], t0[4], b1s[4], b2s[4];
#pragma unroll
    for (int u = 0; u < 4; ++u) {
        const int cls  = popc4(cnotFinv(u) ^ flip) & 3;
        const int c3p  = popc4(cnotFinv(u) ^ flip ^ 11) & 3;  // partner s^8
        const int c0p  = popc4(cnotFinv(u ^ 1) ^ flip) & 3;   // partner s^1
        const int c1p  = popc4(cnotFinv(u ^ 2) ^ flip) & 3;   // partner s^2
        const int c2p  = popc4(cnotFinv(u) ^ flip ^ 12) & 3;  // partner s^4
        sg3[u] = (((c3p + 1 - cls) & 3) == 0) ?  Sv[3] : -Sv[3];
        t0 [u] = (((c0p - cls) & 3) == 0)     ? -Sv[0] :  Sv[0];
        b1s[u] = (((c1p - cls) & 3) == 0)     ?  Sv[1] : -Sv[1];
        b2s[u] = (((c2p - cls) & 3) == 0)     ?  Sv[2] : -Sv[2];
    }
    // effective c/s swap booleans per wire (flip bit w)
    const bool f0 = flip & 1, f1 = flip & 2, f2 = flip & 4, f3 = flip & 8;

    const float sc  = (g == 2) ? -2.f : -1.f;   // tanh for u-gate, sigmoid else
    const float isT = (g == 2) ?  1.f :  0.f;

    float cc[2] = {0.f, 0.f};    // c comps {2*sub, 2*sub+1}
    float hv[2] = {0.f, 0.f};    // h comps {2*sub, 2*sub+1}

    const float2* xp = reinterpret_cast<const float2*>(x);
    const long xb = (long)e * TT * 16 + gl;
    float2 xc = __ldg(&xp[xb]);

#pragma unroll 1
    for (int t = 0; t < TT; ++t) {
        const int tn = (t + 1 < TT) ? t + 1 : t;
        float2 xn = __ldg(&xp[xb + (long)tn * 16]);

        // ---- y: distributed projection, 16-lane butterfly all-reduce ----
        float pw[4];
#pragma unroll
        for (int w = 0; w < 4; ++w) {
            float a = hv[0] * Wh[w][0];
            a = fmaf(hv[1], Wh[w][1], a);
            a = fmaf(xc.x,  Wx[w][0], a);
            a = fmaf(xc.y,  Wx[w][1], a);
            pw[w] = a;
        }
#pragma unroll
        for (int st = 1; st <= 8; st <<= 1)
#pragma unroll
            for (int w = 0; w < 4; ++w) pw[w] += sx(pw[w], st);

        float cw[4], sw[4];
#pragma unroll
        for (int w = 0; w < 4; ++w) __sincosf(pw[w] + hw0[w], &sw[w], &cw[w]);

        // effective factors (lane flip swaps sin/cos roles per wire)
        const float ec0 = f0 ? sw[0] : cw[0], es0 = f0 ? cw[0] : sw[0];
        const float ec1 = f1 ? sw[1] : cw[1], es1 = f1 ? cw[1] : sw[1];
        const float ec2 = f2 ? sw[2] : cw[2], es2 = f2 ? cw[2] : sw[2];
        const float ec3 = f3 ? sw[3] : cw[3];

        // ---- product build: r[u], u = slot low bits, k = Finv(u)^flip ----
        // Finv(0..3) = {0, 3, 6, 5}; bit3 always 0 -> ec3 common
        const float mc = ec2 * ec3, ms = es2 * ec3;
        float r0 = (ec0 * ec1) * mc;
        float r1 = (es0 * es1) * mc;
        float r2 = (ec0 * es1) * ms;
        float r3 = (es0 * ec1) * ms;

        // ---- RX wire3 (mask 8): cross-lane sx(,2), pure-real Givens ----
        {
            float p0 = sx(r0, 2), p1 = sx(r1, 2), p2 = sx(r2, 2), p3 = sx(r3, 2);
            r0 = fmaf(C[3], r0, sg3[0] * p0);
            r1 = fmaf(C[3], r1, sg3[1] * p1);
            r2 = fmaf(C[3], r2, sg3[2] * p2);
            r3 = fmaf(C[3], r3, sg3[3] * p3);
        }
        // ---- RX wire0 (mask 1): local, pure -> complex ----
        float Re[4], Im[4];
        Re[0] = C[0] * r0;  Im[0] = t0[0] * r1;
        Re[1] = C[0] * r1;  Im[1] = t0[1] * r0;
        Re[2] = C[0] * r2;  Im[2] = t0[2] * r3;
        Re[3] = C[0] * r3;  Im[3] = t0[3] * r2;

        // ---- RX wire1 (mask 2): local complex, pairs (0,2),(1,3) ----
#pragma unroll
        for (int u = 0; u < 2; ++u) {
            const int v = u | 2;
            float ar = Re[u], ai = Im[u], br = Re[v], bi = Im[v];
            Re[u] = fmaf(b1s[u], bi, C[1] * ar); Im[u] = fmaf(-b1s[u], br, C[1] * ai);
            Re[v] = fmaf(b1s[v], ai, C[1] * br); Im[v] = fmaf(-b1s[v], ar, C[1] * bi);
        }
        // ---- RX wire2 (mask 4): cross-lane sx(,1), complex ----
#pragma unroll
        for (int u = 0; u < 4; ++u) {
            float rp = sx(Re[u], 1), ip = sx(Im[u], 1);
            Re[u] = fmaf(b2s[u], ip, C[2] * Re[u]);
            Im[u] = fmaf(-b2s[u], rp, C[2] * Im[u]);
        }

        // ---- probabilities + Walsh partials (P1=P2=P3 collapse) ----
        float q0 = fmaf(Re[0], Re[0], Im[0] * Im[0]);
        float q1 = fmaf(Re[1], Re[1], Im[1] * Im[1]);
        float q2 = fmaf(Re[2], Re[2], Im[2] * Im[2]);
        float q3 = fmaf(Re[3], Re[3], Im[3] * Im[3]);
        float d0 = q0 - q2, d1 = q1 - q3;
        float P0 = d0 + d1, P1 = d0 - d1;

        // character-butterfly reduce over 4 sub-lanes (chars folded into Wo)
        float a0 = P0 - sx(P0, 1);                 // parity channel (stage 1)
        float tB = sx(P1, 1);
        float bp = P1 + tB, bm = P1 - tB;
        float ex0 = a0 - sx(a0, 2);                // ~ex0 (parity char)
        float ex1 = bp + sx(bp, 2);                //  ex1 (trivial char)
        float u2  = sx(bm, 2);
        float ex2 = bm + u2;                       // ~ex2 (bit0 char)
        float ex3 = bm - u2;                       // ~ex3 (parity char)

        // ---- activations for own 2 comps ----
        float act0, act1;
        {
            float gv0 = bo[0], gv1 = bo[1];
            gv0 = fmaf(ex0, Wo[0][0], gv0); gv1 = fmaf(ex0, Wo[1][0], gv1);
            gv0 = fmaf(ex1, Wo[0][1], gv0); gv1 = fmaf(ex1, Wo[1][1], gv1);
            gv0 = fmaf(ex2, Wo[0][2], gv0); gv1 = fmaf(ex2, Wo[1][2], gv1);
            gv0 = fmaf(ex3, Wo[0][3], gv0); gv1 = fmaf(ex3, Wo[1][3], gv1);
            float tE0 = __expf(sc * gv0), tE1 = __expf(sc * gv1);
            act0 = __fdividef(fmaf(-isT, tE0, 1.f), 1.f + tE0);
            act1 = __fdividef(fmaf(-isT, tE1, 1.f), 1.f + tE1);
        }

        // ---- gather f,i,u,o (same sub, 4 gate lanes) and update cell ----
        {
            const int s0 = b16 + sub;
            float fv0 = __shfl_sync(FULL, act0, s0);
            float fv1 = __shfl_sync(FULL, act1, s0);
            float iv0 = __shfl_sync(FULL, act0, s0 + 4);
            float iv1 = __shfl_sync(FULL, act1, s0 + 4);
            float uv0 = __shfl_sync(FULL, act0, s0 + 8);
            float uv1 = __shfl_sync(FULL, act1, s0 + 8);
            float ov0 = __shfl_sync(FULL, act0, s0 + 12);
            float ov1 = __shfl_sync(FULL, act1, s0 + 12);

            float c0n = fmaf(fv0, cc[0], iv0 * uv0);
            float c1n = fmaf(fv1, cc[1], iv1 * uv1);
            cc[0] = c0n; cc[1] = c1n;
            c0n = fminf(fmaxf(c0n, -15.f), 15.f);
            c1n = fminf(fmaxf(c1n, -15.f), 15.f);
            float e0v = __expf(-2.f * c0n);
            float e1v = __expf(-2.f * c1n);
            hv[0] = ov0 * __fdividef(1.f - e0v, 1.f + e0v);
            hv[1] = ov1 * __fdividef(1.f - e1v, 1.f + e1v);
        }
        xc = xn;
    }

    // ---- final projection (reduce over sub lanes of gate 0) ----
    float p = hv[0] * __ldg(&w_fc[2 * sub]);
    p = fmaf(hv[1], __ldg(&w_fc[2 * sub + 1]), p);
    p += sx(p, 1);
    p += sx(p, 2);
    if (gl == 0 && e0 < B) out[e0] = p + __ldg(&b_fc[0]);
}

extern "C" void kernel_launch(void* const* d_in, const int* in_sizes, int n_in,
                              void* d_out, int out_size) {
    const float* x     = (const float*)d_in[0];
    const float* w_in  = (const float*)d_in[1];
    const float* b_in  = (const float*)d_in[2];
    const float* w_out = (const float*)d_in[3];
    const float* b_out = (const float*)d_in[4];
    const float* wq_f  = (const float*)d_in[5];
    const float* wq_i  = (const float*)d_in[6];
    const float* wq_u  = (const float*)d_in[7];
    const float* wq_o  = (const float*)d_in[8];
    const float* w_fc  = (const float*)d_in[9];
    const float* b_fc  = (const float*)d_in[10];

    int B = in_sizes[0] / (TT * 32);
    int threads = B * 16;
    int blocks = (threads + 127) / 128;
    qlstm16<<<blocks, 128>>>(x, w_in, b_in, w_out, b_out,
                             wq_f, wq_i, wq_u, wq_o, w_fc, b_fc,
                             (float*)d_out, B);
}